// round 14
// baseline (speedup 1.0000x reference)
#include <cuda_runtime.h>
#include <cuda_fp16.h>
#include <cstdint>
#include <cstddef>

#define NHEADS 12
#define HDIM   64
#define S_LEN  1024
#define BATCH  4
#define HID    768
#define BH     (BATCH * NHEADS)   // 48
#define DROWS  2048
#define MTOT   (BATCH * S_LEN)    // 4096

// ---------------- scratch (__device__ globals; no allocation) ----------------
__device__ __half g_Xh[MTOT * HID];                    // hidden split hi
__device__ __half g_Xl[MTOT * HID];                    // hidden split lo
__device__ __half g_Wh[3 * HID * HID];                 // Wq|Wk|Wv fp16
__device__ __half g_Qh[BH * S_LEN * HDIM];
__device__ __half g_Ql[BH * S_LEN * HDIM];
__device__ __half g_Kh[BH * S_LEN * HDIM];
__device__ float  g_V [BH * S_LEN * HDIM];
__device__ __half g_VTh[BH * HDIM * S_LEN];            // [bh][d][s] hi
__device__ __half g_VTl[BH * HDIM * S_LEN];            // [bh][d][s] lo
__device__ __half g_Dh[DROWS * HDIM];                  // padded dist fp16
__device__ float  g_S[(size_t)BH * S_LEN * S_LEN];     // scores fp32

// ===================== mma.sync / cp.async helpers (sm_80+) ==================
__device__ __forceinline__ uint32_t smem_u32(const void* p) {
    uint32_t a;
    asm("{ .reg .u64 t; cvta.to.shared.u64 t, %1; cvt.u32.u64 %0, t; }"
        : "=r"(a) : "l"(p));
    return a;
}
__device__ __forceinline__ void ldsm_x4(uint32_t r[4], uint32_t addr) {
    asm volatile("ldmatrix.sync.aligned.m8n8.x4.shared.b16 {%0,%1,%2,%3}, [%4];"
                 : "=r"(r[0]), "=r"(r[1]), "=r"(r[2]), "=r"(r[3]) : "r"(addr));
}
__device__ __forceinline__ void mma16816(float* c, const uint32_t a[4],
                                         uint32_t b0, uint32_t b1) {
    asm volatile("mma.sync.aligned.m16n8k16.row.col.f32.f16.f16.f32 "
                 "{%0,%1,%2,%3}, {%4,%5,%6,%7}, {%8,%9}, {%0,%1,%2,%3};"
                 : "+f"(c[0]), "+f"(c[1]), "+f"(c[2]), "+f"(c[3])
                 : "r"(a[0]), "r"(a[1]), "r"(a[2]), "r"(a[3]), "r"(b0), "r"(b1));
}
__device__ __forceinline__ void cp16(void* sdst, const void* gsrc) {
    asm volatile("cp.async.cg.shared.global [%0], [%1], 16;"
                 :: "r"(smem_u32(sdst)), "l"(gsrc));
}
#define CP_COMMIT() asm volatile("cp.async.commit_group;")
#define CP_WAIT1()  asm volatile("cp.async.wait_group 1;")
#define CP_WAIT0()  asm volatile("cp.async.wait_group 0;")

#define LDT 72   // smem tile stride in halfs (144 B: conflict-free ldmatrix)

// Warp GEMM: C[32 x NT*8] += A[32 x 64] * B[NT*8 x 64]^T ; A[m][k], B[n][k].
template<int NT>
__device__ __forceinline__ void wgemm_k64(const __half* As, const __half* Bs,
                                          float* acc, int lane)
{
    #pragma unroll
    for (int k = 0; k < 4; k++) {
        uint32_t a[2][4];
        #pragma unroll
        for (int m = 0; m < 2; m++) {
            uint32_t addr = smem_u32(As + (m * 16 + (lane & 15)) * LDT
                                        + k * 16 + ((lane >> 4) << 3));
            ldsm_x4(a[m], addr);
        }
        uint32_t b[NT][2];
        #pragma unroll
        for (int np = 0; np < NT / 2; np++) {
            uint32_t r[4];
            uint32_t addr = smem_u32(Bs + (np * 16 + (lane & 7) + ((lane >> 4) << 3)) * LDT
                                        + k * 16 + (((lane >> 3) & 1) << 3));
            ldsm_x4(r, addr);
            b[2*np][0] = r[0]; b[2*np][1] = r[1];
            b[2*np+1][0] = r[2]; b[2*np+1][1] = r[3];
        }
        #pragma unroll
        for (int m = 0; m < 2; m++)
            #pragma unroll
            for (int n = 0; n < NT; n++)
                mma16816(acc + (m * NT + n) * 4, a[m], b[n][0], b[n][1]);
    }
}

// synchronous tile copy (scores kernel)
__device__ __forceinline__ void ldtile16(__half* dst, const __half* src,
                                         int rows, int rs, int tid, int nthr) {
    for (int idx = tid; idx < rows * 8; idx += nthr) {
        int r = idx >> 3, v = idx & 7;
        uint4 x = *(const uint4*)(src + (size_t)r * rs + v * 8);
        *(uint4*)(dst + r * LDT + v * 8) = x;
    }
}
// async tile copy via cp.async (16B each)
__device__ __forceinline__ void ldtile_cp(__half* dst, const __half* src,
                                          int rows, int rs, int tid, int nthr) {
    for (int idx = tid; idx < rows * 8; idx += nthr) {
        int r = idx >> 3, v = idx & 7;
        cp16(dst + r * LDT + v * 8, src + (size_t)r * rs + v * 8);
    }
}

__device__ __forceinline__ float fast_exp(float x)
{
    float y = x * 1.4426950408889634f;
    y = fmaxf(y, -120.f);
    float r = rintf(y);
    float f = y - r;
    float z = f * 0.6931471805599453f;
    float p = fmaf(z, 0.008333333f, 0.041666668f);
    p = fmaf(z, p, 0.16666667f);
    p = fmaf(z, p, 0.5f);
    p = fmaf(z, p, 1.0f);
    p = fmaf(z, p, 1.0f);
    int e = (int)r;
    float s = __int_as_float((e + 127) << 23);
    return s * p;
}

// =============================================================================
// Prep kernels
// =============================================================================
__global__ __launch_bounds__(256) void split_x_kernel(const float* __restrict__ X)
{
    int idx = blockIdx.x * 256 + threadIdx.x;
    float v = X[idx];
    __half h = __float2half(v);
    g_Xh[idx] = h;
    g_Xl[idx] = __float2half(v - __half2float(h));
}
__global__ __launch_bounds__(256) void conv_w_kernel(
    const float* __restrict__ Wq, const float* __restrict__ Wk,
    const float* __restrict__ Wv)
{
    int z = blockIdx.y;
    const float* W = (z == 0) ? Wq : (z == 1) ? Wk : Wv;
    int idx = blockIdx.x * 256 + threadIdx.x;
    g_Wh[z * HID * HID + idx] = __float2half(W[idx]);
}
__global__ __launch_bounds__(256) void prep_dist_kernel(const float* __restrict__ dist)
{
    int idx = blockIdx.x * 256 + threadIdx.x;
    int t = idx >> 6;
    float v = (t < 2047) ? dist[idx] : 0.f;
    g_Dh[idx] = __float2half(v);
}

// =============================================================================
// Kernel 1: QKV projection, 2-term compensated (XhWh + XlWh), cp.async
// double-buffered.  128(m) x 64(n) tile / CTA, 256 threads, 2 CTAs/SM.
// =============================================================================
#define QKV_BUF  27648
#define QKV_SMEM (2 * 55296)
__global__ __launch_bounds__(256) void qkv_mma_kernel(
    const float* __restrict__ bq, const float* __restrict__ bk,
    const float* __restrict__ bv)
{
    extern __shared__ __half sh[];
    int tid = threadIdx.x, wid = tid >> 5, lane = tid & 31;
    int wm = wid >> 1, wn = wid & 1;
    int m0 = blockIdx.x << 7, n0 = blockIdx.y << 6;
    int z = blockIdx.z;
    const float* bias = (z == 0) ? bq : (z == 1) ? bk : bv;

    const __half* Xhp = g_Xh + (size_t)m0 * HID;
    const __half* Xlp = g_Xl + (size_t)m0 * HID;
    const __half* Whp = g_Wh + (size_t)z * HID * HID + (size_t)n0 * HID;

    float acc[32];
    #pragma unroll
    for (int i = 0; i < 32; i++) acc[i] = 0.f;

    {
        __half* B = sh;
        ldtile_cp(B,             Xhp, 128, HID, tid, 256);
        ldtile_cp(B + 128 * LDT, Xlp, 128, HID, tid, 256);
        ldtile_cp(B + 256 * LDT, Whp,  64, HID, tid, 256);
        CP_COMMIT();
    }

    for (int c = 0; c < 12; c++) {
        __half* cur = sh + (c & 1) * QKV_BUF;
        if (c + 1 < 12) {
            __half* nxt = sh + ((c + 1) & 1) * QKV_BUF;
            int kt = (c + 1) * 64;
            ldtile_cp(nxt,             Xhp + kt, 128, HID, tid, 256);
            ldtile_cp(nxt + 128 * LDT, Xlp + kt, 128, HID, tid, 256);
            ldtile_cp(nxt + 256 * LDT, Whp + kt,  64, HID, tid, 256);
            CP_COMMIT();
            CP_WAIT1();
        } else {
            CP_WAIT0();
        }
        __syncthreads();
        wgemm_k64<4>(cur + wm * 32 * LDT,             cur + 256 * LDT + wn * 32 * LDT, acc, lane);
        wgemm_k64<4>(cur + 128 * LDT + wm * 32 * LDT, cur + 256 * LDT + wn * 32 * LDT, acc, lane);
        __syncthreads();
    }

    #pragma unroll
    for (int m = 0; m < 2; m++)
        #pragma unroll
        for (int n = 0; n < 4; n++) {
            float* c = acc + (m * 4 + n) * 4;
            int mrow = m0 + wm * 32 + m * 16 + (lane >> 2);
            int ncol = n0 + wn * 32 + n * 8 + ((lane & 3) << 1);
            #pragma unroll
            for (int hi = 0; hi < 2; hi++) {
                int mr = mrow + hi * 8;
                int bb = mr >> 10, s = mr & 1023;
                #pragma unroll
                for (int cc = 0; cc < 2; cc++) {
                    int n_g = ncol + cc;
                    int h = n_g >> 6, d = n_g & 63;
                    size_t idx = (((size_t)(bb * NHEADS + h)) * S_LEN + s) * HDIM + d;
                    float val = c[hi * 2 + cc] + bias[n_g];
                    if (z == 2) {
                        g_V[idx] = val;
                    } else if (z == 1) {
                        g_Kh[idx] = __float2half(val);
                    } else {
                        __half hv = __float2half(val);
                        g_Qh[idx] = hv;
                        g_Ql[idx] = __float2half(val - __half2float(hv));
                    }
                }
            }
        }
}

// =============================================================================
// Kernel 1c: V transpose [bh][s][d] f32 -> [bh][d][s] fp16 hi/lo
// =============================================================================
__global__ __launch_bounds__(256) void vt_kernel()
{
    __shared__ float st[64 * 65];
    int bh = blockIdx.y, s0 = blockIdx.x << 6;
    const float* Vp = g_V + (size_t)bh * (S_LEN * HDIM);
    for (int idx = threadIdx.x; idx < 4096; idx += 256) {
        int sl = idx >> 6, d = idx & 63;
        st[d * 65 + sl] = Vp[(size_t)(s0 + sl) * 64 + d];
    }
    __syncthreads();
    for (int idx = threadIdx.x; idx < 4096; idx += 256) {
        int d = idx >> 6, sl = idx & 63;
        float v = st[d * 65 + sl];
        __half hv = __float2half(v);
        size_t o = ((size_t)bh * 64 + d) * S_LEN + s0 + sl;
        g_VTh[o] = hv;
        g_VTl[o] = __float2half(v - __half2float(hv));
    }
}

// =============================================================================
// Kernel 2: scores, 128(l) x 64(r) tile / CTA, 2 CTAs/SM (109.8 KB smem).
//   j = ll - rr + 63 in [0,190]; window Dw = D[t0 .. t0+191], t0 = l0-r0+960.
//   Bands in diagonal form: CqD[ll][rr], CkD[rr][ll].
//   epilogue: (QK + CqD + CkD) * 0.125 + mask[rr] -> g_S fp32
// =============================================================================
#define CKD_LD 136
#define SC_SMEM 109824
__global__ __launch_bounds__(256, 2) void scores_mma_kernel(const float* __restrict__ mask)
{
    extern __shared__ __half sh[];
    __half* Qh  = sh;
    __half* Ql  = sh + 9216;
    __half* Kh  = sh + 18432;
    __half* Dw  = sh + 23040;
    __half* CqD = sh + 36864;
    __half* CkD = sh + 46080;
    float*  mask_s = (float*)((char*)sh + 109568);

    int tid = threadIdx.x, wid = tid >> 5, lane = tid & 31;
    int bh = blockIdx.z, b = bh / NHEADS;
    int l0 = blockIdx.y << 7, r0 = blockIdx.x << 6;
    int t0 = l0 - r0 + 960;

    size_t qoff = (size_t)bh * (S_LEN * HDIM) + (size_t)l0 * 64;
    size_t koff = (size_t)bh * (S_LEN * HDIM) + (size_t)r0 * 64;
    ldtile16(Qh, g_Qh + qoff, 128, 64, tid, 256);
    ldtile16(Ql, g_Ql + qoff, 128, 64, tid, 256);
    ldtile16(Kh, g_Kh + koff,  64, 64, tid, 256);
    ldtile16(Dw, g_Dh + (size_t)t0 * 64, 192, 64, tid, 256);
    if (tid < 64) mask_s[tid] = mask[b * S_LEN + r0 + tid];
    __syncthreads();

    {
        int wm = wid >> 1, wj = wid & 1;
        #pragma unroll
        for (int p = 0; p < 2; p++) {
            float acc[48];
            #pragma unroll
            for (int i = 0; i < 48; i++) acc[i] = 0.f;
            int jb = wj * 96 + p * 48;
            wgemm_k64<6>(Qh + wm * 32 * LDT, Dw + jb * LDT, acc, lane);
            #pragma unroll
            for (int m = 0; m < 2; m++)
                #pragma unroll
                for (int n = 0; n < 6; n++) {
                    float* c = acc + (m * 6 + n) * 4;
                    int row = wm * 32 + m * 16 + (lane >> 2);
                    int j   = jb + n * 8 + ((lane & 3) << 1);
                    int rr0 = row + 63 - j;
                    if ((unsigned)rr0 < 64u)     CqD[row * LDT + rr0]           = __float2half(c[0]);
                    if ((unsigned)(rr0-1) < 64u) CqD[row * LDT + rr0 - 1]       = __float2half(c[1]);
                    if ((unsigned)(rr0+8) < 64u) CqD[(row + 8) * LDT + rr0 + 8] = __float2half(c[2]);
                    if ((unsigned)(rr0+7) < 64u) CqD[(row + 8) * LDT + rr0 + 7] = __float2half(c[3]);
                }
        }
    }
    {
        int wr = wid >> 2, wj4 = wid & 3;
        float acc[48];
        #pragma unroll
        for (int i = 0; i < 48; i++) acc[i] = 0.f;
        int jb = wj4 * 48;
        wgemm_k64<6>(Kh + wr * 32 * LDT, Dw + jb * LDT, acc, lane);
        #pragma unroll
        for (int m = 0; m < 2; m++)
            #pragma unroll
            for (int n = 0; n < 6; n++) {
                float* c = acc + (m * 6 + n) * 4;
                int rr = wr * 32 + m * 16 + (lane >> 2);
                int j  = jb + n * 8 + ((lane & 3) << 1);
                int ll0 = j + rr - 63;
                if ((unsigned)ll0 < 128u)     CkD[rr * CKD_LD + ll0]           = __float2half(c[0]);
                if ((unsigned)(ll0+1) < 128u) CkD[rr * CKD_LD + ll0 + 1]       = __float2half(c[1]);
                if ((unsigned)(ll0+8) < 128u) CkD[(rr + 8) * CKD_LD + ll0 + 8] = __float2half(c[2]);
                if ((unsigned)(ll0+9) < 128u) CkD[(rr + 8) * CKD_LD + ll0 + 9] = __float2half(c[3]);
            }
    }

    int wm = wid >> 1, wn = wid & 1;
    float acc[32];
    #pragma unroll
    for (int i = 0; i < 32; i++) acc[i] = 0.f;
    wgemm_k64<4>(Qh + wm * 32 * LDT, Kh + wn * 32 * LDT, acc, lane);
    wgemm_k64<4>(Ql + wm * 32 * LDT, Kh + wn * 32 * LDT, acc, lane);
    __syncthreads();

    #pragma unroll
    for (int m = 0; m < 2; m++)
        #pragma unroll
        for (int n = 0; n < 4; n++) {
            float* c = acc + (m * 4 + n) * 4;
            int lrow = wm * 32 + m * 16 + (lane >> 2);
            int rr   = wn * 32 + n * 8 + ((lane & 3) << 1);
            #pragma unroll
            for (int hi = 0; hi < 2; hi++) {
                int ll = lrow + hi * 8;
                float s0 = (c[hi * 2 + 0]
                            + __half2float(CqD[ll * LDT + rr])
                            + __half2float(CkD[rr * CKD_LD + ll])) * 0.125f
                           + mask_s[rr];
                float s1 = (c[hi * 2 + 1]
                            + __half2float(CqD[ll * LDT + rr + 1])
                            + __half2float(CkD[(rr + 1) * CKD_LD + ll])) * 0.125f
                           + mask_s[rr + 1];
                *(float2*)(g_S + ((size_t)bh * S_LEN + l0 + ll) * S_LEN + r0 + rr)
                    = make_float2(s0, s1);
            }
        }
}

// =============================================================================
// Kernel 3 (fused softmax + PV): per CTA = (bh, 128 l-rows).
// Phase 1: stream S rows, compute rowmax m and inv = 1/sum(exp(s-m)) -> smem.
// Phase 2: loop 16 r-tiles: cp.async S tile (fp32) + V tiles; stage
//   p = exp(s-m)*inv, split fp16 hi/lo into LDT-layout smem; 3-term wgemm.
// smem bytes: Sraw f32 128x68 @0 (34816) | Pth @34816 | Ptl @53248 (18432 ea)
//   | V bufs @71680 (4 x 9216: Vh0,Vl0,Vh1,Vl1) | m_s @108544 | is_s @109056
// total 109568 -> 2 CTAs/SM.
// =============================================================================
#define AT_SMEM 109568
__global__ __launch_bounds__(256, 2) void attn_pv_kernel(float* __restrict__ out)
{
    extern __shared__ char smraw[];
    float*  Sraw = (float*)smraw;                       // 128 x 68
    __half* Pth  = (__half*)(smraw + 34816);            // 128 x LDT
    __half* Ptl  = (__half*)(smraw + 53248);            // 128 x LDT
    __half* Vbuf = (__half*)(smraw + 71680);            // 4 x (64 x LDT)
    float*  m_s  = (float*)(smraw + 108544);            // 128
    float*  is_s = (float*)(smraw + 109056);            // 128

    int tid = threadIdx.x, wid = tid >> 5, lane = tid & 31;
    int wm = wid >> 1, wn = wid & 1;
    int bh = blockIdx.y, l0 = blockIdx.x << 7;
    int b = bh / NHEADS, h = bh % NHEADS;

    const float* Sp  = g_S + ((size_t)bh * S_LEN + l0) * S_LEN;
    const __half* Vhp = g_VTh + (size_t)bh * (HDIM * S_LEN);
    const __half* Vlp = g_VTl + (size_t)bh * (HDIM * S_LEN);

    // ---- Phase 1: row stats (warp = 16 rows) ----
    for (int rr = 0; rr < 16; rr++) {
        int row = wid * 16 + rr;
        const float4* rp = (const float4*)(Sp + (size_t)row * S_LEN);
        float4 v[8];
        #pragma unroll
        for (int k = 0; k < 8; k++) v[k] = rp[lane + (k << 5)];
        float m = fmaxf(fmaxf(v[0].x, v[0].y), fmaxf(v[0].z, v[0].w));
        #pragma unroll
        for (int k = 1; k < 8; k++)
            m = fmaxf(m, fmaxf(fmaxf(v[k].x, v[k].y), fmaxf(v[k].z, v[k].w)));
        #pragma unroll
        for (int o = 16; o; o >>= 1) m = fmaxf(m, __shfl_xor_sync(0xffffffffu, m, o));
        float s = 0.f;
        #pragma unroll
        for (int k = 0; k < 8; k++) {
            s += fast_exp(v[k].x - m) + fast_exp(v[k].y - m)
               + fast_exp(v[k].z - m) + fast_exp(v[k].w - m);
        }
        #pragma unroll
        for (int o = 16; o; o >>= 1) s += __shfl_xor_sync(0xffffffffu, s, o);
        if (lane == 0) { m_s[row] = m; is_s[row] = 1.0f / s; }
    }
    __syncthreads();

    // ---- Phase 2: tiled PV with on-the-fly P staging ----
    float acc[32];
    #pragma unroll
    for (int i = 0; i < 32; i++) acc[i] = 0.f;

    // prefetch tile 0: S raw + V bufs
    {
        for (int idx = tid; idx < 2048; idx += 256) {       // 128 rows x 16 chunks
            int r = idx >> 4, v = idx & 15;
            cp16(Sraw + r * 68 + v * 4, Sp + (size_t)r * S_LEN + v * 4);
        }
        ldtile_cp(Vbuf,            Vhp, 64, S_LEN, tid, 256);
        ldtile_cp(Vbuf + 64 * LDT, Vlp, 64, S_LEN, tid, 256);
        CP_COMMIT();
    }

    for (int c = 0; c < 16; c++) {
        __half* Vh = Vbuf + (c & 1) * (128 * LDT);
        __half* Vl = Vh + 64 * LDT;
        CP_WAIT0();
        __syncthreads();

        // stage P tile: p = exp(s - m) * inv, hi/lo split
        {
            int row = tid >> 1, cp0 = (tid & 1) << 5;
            float m = m_s[row], inv = is_s[row];
            #pragma unroll
            for (int j = 0; j < 8; j++) {
                int col = cp0 + j * 4;
                float4 s4 = *(float4*)(Sraw + row * 68 + col);
                float p0 = fast_exp(s4.x - m) * inv;
                float p1 = fast_exp(s4.y - m) * inv;
                float p2 = fast_exp(s4.z - m) * inv;
                float p3 = fast_exp(s4.w - m) * inv;
                __half h0 = __float2half(p0), h1 = __float2half(p1);
                __half h2 = __float2half(p2), h3 = __float2half(p3);
                *(half2*)(Pth + row * LDT + col)     = __halves2half2(h0, h1);
                *(half2*)(Pth + row * LDT + col + 2) = __halves2half2(h2, h3);
                *(half2*)(Ptl + row * LDT + col) = __halves2half2(
                    __float2half(p0 - __half2float(h0)),
                    __float2half(p1 - __half2float(h1)));
                *(half2*)(Ptl + row * LDT + col + 2) = __halves2half2(
                    __float2half(p2 - __half2float(h2)),
                    __float2half(p3 - __half2float(h3)));
            }
        }
        __syncthreads();

        // prefetch next tile (S into the single Sraw buffer — safe: all
        // threads finished reading it at the sync above; V double-buffered)
        if (c + 1 < 16) {
            int kt = (c + 1) * 64;
            for (int idx = tid; idx < 2048; idx += 256) {
                int r = idx >> 4, v = idx & 15;
                cp16(Sraw + r * 68 + v * 4, Sp + (size_t)r * S_LEN + kt + v * 4);
            }
            __half* nVh = Vbuf + ((c + 1) & 1) * (128 * LDT);
            ldtile_cp(nVh,            Vhp + kt, 64, S_LEN, tid, 256);
            ldtile_cp(nVh + 64 * LDT, Vlp + kt, 64, S_LEN, tid, 256);
            CP_COMMIT();
        }

        wgemm_k64<4>(Pth + wm * 32 * LDT, Vh + wn * 32 * LDT, acc, lane);
        wgemm_k64<4>(Ptl + wm * 32 * LDT, Vh + wn * 32 * LDT, acc, lane);
        wgemm_k64<4>(Pth + wm * 32 * LDT, Vl + wn * 32 * LDT, acc, lane);
        __syncthreads();
    }

    #pragma unroll
    for (int m = 0; m < 2; m++)
        #pragma unroll
        for (int n = 0; n < 4; n++) {
            float* c = acc + (m * 4 + n) * 4;
            int lrow = wm * 32 + m * 16 + (lane >> 2);
            int d    = wn * 32 + n * 8 + ((lane & 3) << 1);
            float* o0 = out + ((size_t)b * S_LEN + l0 + lrow) * HID + h * HDIM + d;
            *(float2*)o0 = make_float2(c[0], c[1]);
            float* o1 = o0 + 8 * HID;
            *(float2*)o1 = make_float2(c[2], c[3]);
        }
}

// =============================================================================
extern "C" void kernel_launch(void* const* d_in, const int* in_sizes, int n_in,
                              void* d_out, int out_size)
{
    const float* hidden = (const float*)d_in[0];
    const float* mask   = (const float*)d_in[1];
    const float* Wq     = (const float*)d_in[2];
    const float* bq     = (const float*)d_in[3];
    const float* Wk     = (const float*)d_in[4];
    const float* bk     = (const float*)d_in[5];
    const float* Wv     = (const float*)d_in[6];
    const float* bv     = (const float*)d_in[7];
    const float* dist   = (const float*)d_in[8];
    float* out          = (float*)d_out;

    cudaFuncSetAttribute(qkv_mma_kernel,
                         cudaFuncAttributeMaxDynamicSharedMemorySize, QKV_SMEM);
    cudaFuncSetAttribute(scores_mma_kernel,
                         cudaFuncAttributeMaxDynamicSharedMemorySize, SC_SMEM);
    cudaFuncSetAttribute(attn_pv_kernel,
                         cudaFuncAttributeMaxDynamicSharedMemorySize, AT_SMEM);

    split_x_kernel<<<(MTOT * HID) / 256, 256>>>(hidden);
    conv_w_kernel<<<dim3((HID * HID) / 256, 3), 256>>>(Wq, Wk, Wv);
    prep_dist_kernel<<<(DROWS * 64) / 256, 256>>>(dist);
    qkv_mma_kernel<<<dim3(32, 12, 3), 256, QKV_SMEM>>>(bq, bk, bv);
    vt_kernel<<<dim3(16, BH), 256>>>();
    scores_mma_kernel<<<dim3(16, 8, BH), 256, SC_SMEM>>>(mask);
    attn_pv_kernel<<<dim3(8, BH), 256, AT_SMEM>>>(out);
}

// round 15
// speedup vs baseline: 1.1806x; 1.1806x over previous
#include <cuda_runtime.h>
#include <cuda_fp16.h>
#include <cstdint>
#include <cstddef>

#define NHEADS 12
#define HDIM   64
#define S_LEN  1024
#define BATCH  4
#define HID    768
#define BH     (BATCH * NHEADS)   // 48
#define DROWS  2048
#define MTOT   (BATCH * S_LEN)    // 4096

// ---------------- scratch (__device__ globals; no allocation) ----------------
__device__ __half g_Xh[MTOT * HID];                    // hidden split hi
__device__ __half g_Xl[MTOT * HID];                    // hidden split lo
__device__ __half g_Wh[3 * HID * HID];                 // Wq|Wk|Wv fp16
__device__ __half g_Qh[BH * S_LEN * HDIM];
__device__ __half g_Ql[BH * S_LEN * HDIM];
__device__ __half g_Kh[BH * S_LEN * HDIM];
__device__ float  g_V [BH * S_LEN * HDIM];
__device__ __half g_VTh[BH * HDIM * S_LEN];            // [bh][d][s] hi
__device__ __half g_VTl[BH * HDIM * S_LEN];            // [bh][d][s] lo
__device__ __half g_Dh[DROWS * HDIM];                  // padded dist fp16
__device__ float  g_S[(size_t)BH * S_LEN * S_LEN];     // scores fp32
__device__ __half g_Ph[(size_t)BH * S_LEN * S_LEN];    // probs fp16 (hi only)

// ===================== mma.sync / cp.async helpers (sm_80+) ==================
__device__ __forceinline__ uint32_t smem_u32(const void* p) {
    uint32_t a;
    asm("{ .reg .u64 t; cvta.to.shared.u64 t, %1; cvt.u32.u64 %0, t; }"
        : "=r"(a) : "l"(p));
    return a;
}
__device__ __forceinline__ void ldsm_x4(uint32_t r[4], uint32_t addr) {
    asm volatile("ldmatrix.sync.aligned.m8n8.x4.shared.b16 {%0,%1,%2,%3}, [%4];"
                 : "=r"(r[0]), "=r"(r[1]), "=r"(r[2]), "=r"(r[3]) : "r"(addr));
}
__device__ __forceinline__ void mma16816(float* c, const uint32_t a[4],
                                         uint32_t b0, uint32_t b1) {
    asm volatile("mma.sync.aligned.m16n8k16.row.col.f32.f16.f16.f32 "
                 "{%0,%1,%2,%3}, {%4,%5,%6,%7}, {%8,%9}, {%0,%1,%2,%3};"
                 : "+f"(c[0]), "+f"(c[1]), "+f"(c[2]), "+f"(c[3])
                 : "r"(a[0]), "r"(a[1]), "r"(a[2]), "r"(a[3]), "r"(b0), "r"(b1));
}
__device__ __forceinline__ void cp16(void* sdst, const void* gsrc) {
    asm volatile("cp.async.cg.shared.global [%0], [%1], 16;"
                 :: "r"(smem_u32(sdst)), "l"(gsrc));
}
#define CP_COMMIT() asm volatile("cp.async.commit_group;")
#define CP_WAIT1()  asm volatile("cp.async.wait_group 1;")
#define CP_WAIT0()  asm volatile("cp.async.wait_group 0;")

#define LDT 72   // smem tile stride in halfs (144 B: conflict-free ldmatrix)

// Warp GEMM: C[32 x NT*8] += A[32 x 64] * B[NT*8 x 64]^T ; A[m][k], B[n][k].
template<int NT>
__device__ __forceinline__ void wgemm_k64(const __half* As, const __half* Bs,
                                          float* acc, int lane)
{
    #pragma unroll
    for (int k = 0; k < 4; k++) {
        uint32_t a[2][4];
        #pragma unroll
        for (int m = 0; m < 2; m++) {
            uint32_t addr = smem_u32(As + (m * 16 + (lane & 15)) * LDT
                                        + k * 16 + ((lane >> 4) << 3));
            ldsm_x4(a[m], addr);
        }
        uint32_t b[NT][2];
        #pragma unroll
        for (int np = 0; np < NT / 2; np++) {
            uint32_t r[4];
            uint32_t addr = smem_u32(Bs + (np * 16 + (lane & 7) + ((lane >> 4) << 3)) * LDT
                                        + k * 16 + (((lane >> 3) & 1) << 3));
            ldsm_x4(r, addr);
            b[2*np][0] = r[0]; b[2*np][1] = r[1];
            b[2*np+1][0] = r[2]; b[2*np+1][1] = r[3];
        }
        #pragma unroll
        for (int m = 0; m < 2; m++)
            #pragma unroll
            for (int n = 0; n < NT; n++)
                mma16816(acc + (m * NT + n) * 4, a[m], b[n][0], b[n][1]);
    }
}

// synchronous tile copy (scores kernel)
__device__ __forceinline__ void ldtile16(__half* dst, const __half* src,
                                         int rows, int rs, int tid, int nthr) {
    for (int idx = tid; idx < rows * 8; idx += nthr) {
        int r = idx >> 3, v = idx & 7;
        uint4 x = *(const uint4*)(src + (size_t)r * rs + v * 8);
        *(uint4*)(dst + r * LDT + v * 8) = x;
    }
}
// async tile copy via cp.async (16B each)
__device__ __forceinline__ void ldtile_cp(__half* dst, const __half* src,
                                          int rows, int rs, int tid, int nthr) {
    for (int idx = tid; idx < rows * 8; idx += nthr) {
        int r = idx >> 3, v = idx & 7;
        cp16(dst + r * LDT + v * 8, src + (size_t)r * rs + v * 8);
    }
}

__device__ __forceinline__ float fast_exp(float x)
{
    float y = x * 1.4426950408889634f;
    y = fmaxf(y, -120.f);
    float r = rintf(y);
    float f = y - r;
    float z = f * 0.6931471805599453f;
    float p = fmaf(z, 0.008333333f, 0.041666668f);
    p = fmaf(z, p, 0.16666667f);
    p = fmaf(z, p, 0.5f);
    p = fmaf(z, p, 1.0f);
    p = fmaf(z, p, 1.0f);
    int e = (int)r;
    float s = __int_as_float((e + 127) << 23);
    return s * p;
}

// =============================================================================
// Prep kernels
// =============================================================================
__global__ __launch_bounds__(256) void split_x_kernel(const float* __restrict__ X)
{
    int idx = blockIdx.x * 256 + threadIdx.x;
    float v = X[idx];
    __half h = __float2half(v);
    g_Xh[idx] = h;
    g_Xl[idx] = __float2half(v - __half2float(h));
}
__global__ __launch_bounds__(256) void conv_w_kernel(
    const float* __restrict__ Wq, const float* __restrict__ Wk,
    const float* __restrict__ Wv)
{
    int z = blockIdx.y;
    const float* W = (z == 0) ? Wq : (z == 1) ? Wk : Wv;
    int idx = blockIdx.x * 256 + threadIdx.x;
    g_Wh[z * HID * HID + idx] = __float2half(W[idx]);
}
__global__ __launch_bounds__(256) void prep_dist_kernel(const float* __restrict__ dist)
{
    int idx = blockIdx.x * 256 + threadIdx.x;
    int t = idx >> 6;
    float v = (t < 2047) ? dist[idx] : 0.f;
    g_Dh[idx] = __float2half(v);
}

// =============================================================================
// Kernel 1: QKV projection, 2-term compensated (XhWh + XlWh), cp.async
// double-buffered.  128(m) x 64(n) tile / CTA, 256 threads, 2 CTAs/SM.
// =============================================================================
#define QKV_BUF  27648
#define QKV_SMEM (2 * 55296)
__global__ __launch_bounds__(256) void qkv_mma_kernel(
    const float* __restrict__ bq, const float* __restrict__ bk,
    const float* __restrict__ bv)
{
    extern __shared__ __half sh[];
    int tid = threadIdx.x, wid = tid >> 5, lane = tid & 31;
    int wm = wid >> 1, wn = wid & 1;
    int m0 = blockIdx.x << 7, n0 = blockIdx.y << 6;
    int z = blockIdx.z;
    const float* bias = (z == 0) ? bq : (z == 1) ? bk : bv;

    const __half* Xhp = g_Xh + (size_t)m0 * HID;
    const __half* Xlp = g_Xl + (size_t)m0 * HID;
    const __half* Whp = g_Wh + (size_t)z * HID * HID + (size_t)n0 * HID;

    float acc[32];
    #pragma unroll
    for (int i = 0; i < 32; i++) acc[i] = 0.f;

    {
        __half* B = sh;
        ldtile_cp(B,             Xhp, 128, HID, tid, 256);
        ldtile_cp(B + 128 * LDT, Xlp, 128, HID, tid, 256);
        ldtile_cp(B + 256 * LDT, Whp,  64, HID, tid, 256);
        CP_COMMIT();
    }

    for (int c = 0; c < 12; c++) {
        __half* cur = sh + (c & 1) * QKV_BUF;
        if (c + 1 < 12) {
            __half* nxt = sh + ((c + 1) & 1) * QKV_BUF;
            int kt = (c + 1) * 64;
            ldtile_cp(nxt,             Xhp + kt, 128, HID, tid, 256);
            ldtile_cp(nxt + 128 * LDT, Xlp + kt, 128, HID, tid, 256);
            ldtile_cp(nxt + 256 * LDT, Whp + kt,  64, HID, tid, 256);
            CP_COMMIT();
            CP_WAIT1();
        } else {
            CP_WAIT0();
        }
        __syncthreads();
        wgemm_k64<4>(cur + wm * 32 * LDT,             cur + 256 * LDT + wn * 32 * LDT, acc, lane);
        wgemm_k64<4>(cur + 128 * LDT + wm * 32 * LDT, cur + 256 * LDT + wn * 32 * LDT, acc, lane);
        __syncthreads();
    }

    #pragma unroll
    for (int m = 0; m < 2; m++)
        #pragma unroll
        for (int n = 0; n < 4; n++) {
            float* c = acc + (m * 4 + n) * 4;
            int mrow = m0 + wm * 32 + m * 16 + (lane >> 2);
            int ncol = n0 + wn * 32 + n * 8 + ((lane & 3) << 1);
            #pragma unroll
            for (int hi = 0; hi < 2; hi++) {
                int mr = mrow + hi * 8;
                int bb = mr >> 10, s = mr & 1023;
                #pragma unroll
                for (int cc = 0; cc < 2; cc++) {
                    int n_g = ncol + cc;
                    int h = n_g >> 6, d = n_g & 63;
                    size_t idx = (((size_t)(bb * NHEADS + h)) * S_LEN + s) * HDIM + d;
                    float val = c[hi * 2 + cc] + bias[n_g];
                    if (z == 2) {
                        g_V[idx] = val;
                    } else if (z == 1) {
                        g_Kh[idx] = __float2half(val);
                    } else {
                        __half hv = __float2half(val);
                        g_Qh[idx] = hv;
                        g_Ql[idx] = __float2half(val - __half2float(hv));
                    }
                }
            }
        }
}

// =============================================================================
// Kernel 1c: V transpose [bh][s][d] f32 -> [bh][d][s] fp16 hi/lo
// =============================================================================
__global__ __launch_bounds__(256) void vt_kernel()
{
    __shared__ float st[64 * 65];
    int bh = blockIdx.y, s0 = blockIdx.x << 6;
    const float* Vp = g_V + (size_t)bh * (S_LEN * HDIM);
    for (int idx = threadIdx.x; idx < 4096; idx += 256) {
        int sl = idx >> 6, d = idx & 63;
        st[d * 65 + sl] = Vp[(size_t)(s0 + sl) * 64 + d];
    }
    __syncthreads();
    for (int idx = threadIdx.x; idx < 4096; idx += 256) {
        int d = idx >> 6, sl = idx & 63;
        float v = st[d * 65 + sl];
        __half hv = __float2half(v);
        size_t o = ((size_t)bh * 64 + d) * S_LEN + s0 + sl;
        g_VTh[o] = hv;
        g_VTl[o] = __float2half(v - __half2float(hv));
    }
}

// =============================================================================
// Kernel 2: scores, 128(l) x 64(r) tile / CTA, 2 CTAs/SM (109.8 KB smem).
//   j = ll - rr + 63 in [0,190]; window Dw = D[t0 .. t0+191], t0 = l0-r0+960.
//   Bands in diagonal form: CqD[ll][rr], CkD[rr][ll].
//   epilogue: (QK + CqD + CkD) * 0.125 + mask[rr] -> g_S fp32
// =============================================================================
#define CKD_LD 136
#define SC_SMEM 109824
__global__ __launch_bounds__(256, 2) void scores_mma_kernel(const float* __restrict__ mask)
{
    extern __shared__ __half sh[];
    __half* Qh  = sh;
    __half* Ql  = sh + 9216;
    __half* Kh  = sh + 18432;
    __half* Dw  = sh + 23040;
    __half* CqD = sh + 36864;
    __half* CkD = sh + 46080;
    float*  mask_s = (float*)((char*)sh + 109568);

    int tid = threadIdx.x, wid = tid >> 5, lane = tid & 31;
    int bh = blockIdx.z, b = bh / NHEADS;
    int l0 = blockIdx.y << 7, r0 = blockIdx.x << 6;
    int t0 = l0 - r0 + 960;

    size_t qoff = (size_t)bh * (S_LEN * HDIM) + (size_t)l0 * 64;
    size_t koff = (size_t)bh * (S_LEN * HDIM) + (size_t)r0 * 64;
    ldtile16(Qh, g_Qh + qoff, 128, 64, tid, 256);
    ldtile16(Ql, g_Ql + qoff, 128, 64, tid, 256);
    ldtile16(Kh, g_Kh + koff,  64, 64, tid, 256);
    ldtile16(Dw, g_Dh + (size_t)t0 * 64, 192, 64, tid, 256);
    if (tid < 64) mask_s[tid] = mask[b * S_LEN + r0 + tid];
    __syncthreads();

    {
        int wm = wid >> 1, wj = wid & 1;
        #pragma unroll
        for (int p = 0; p < 2; p++) {
            float acc[48];
            #pragma unroll
            for (int i = 0; i < 48; i++) acc[i] = 0.f;
            int jb = wj * 96 + p * 48;
            wgemm_k64<6>(Qh + wm * 32 * LDT, Dw + jb * LDT, acc, lane);
            #pragma unroll
            for (int m = 0; m < 2; m++)
                #pragma unroll
                for (int n = 0; n < 6; n++) {
                    float* c = acc + (m * 6 + n) * 4;
                    int row = wm * 32 + m * 16 + (lane >> 2);
                    int j   = jb + n * 8 + ((lane & 3) << 1);
                    int rr0 = row + 63 - j;
                    if ((unsigned)rr0 < 64u)     CqD[row * LDT + rr0]           = __float2half(c[0]);
                    if ((unsigned)(rr0-1) < 64u) CqD[row * LDT + rr0 - 1]       = __float2half(c[1]);
                    if ((unsigned)(rr0+8) < 64u) CqD[(row + 8) * LDT + rr0 + 8] = __float2half(c[2]);
                    if ((unsigned)(rr0+7) < 64u) CqD[(row + 8) * LDT + rr0 + 7] = __float2half(c[3]);
                }
        }
    }
    {
        int wr = wid >> 2, wj4 = wid & 3;
        float acc[48];
        #pragma unroll
        for (int i = 0; i < 48; i++) acc[i] = 0.f;
        int jb = wj4 * 48;
        wgemm_k64<6>(Kh + wr * 32 * LDT, Dw + jb * LDT, acc, lane);
        #pragma unroll
        for (int m = 0; m < 2; m++)
            #pragma unroll
            for (int n = 0; n < 6; n++) {
                float* c = acc + (m * 6 + n) * 4;
                int rr = wr * 32 + m * 16 + (lane >> 2);
                int j  = jb + n * 8 + ((lane & 3) << 1);
                int ll0 = j + rr - 63;
                if ((unsigned)ll0 < 128u)     CkD[rr * CKD_LD + ll0]           = __float2half(c[0]);
                if ((unsigned)(ll0+1) < 128u) CkD[rr * CKD_LD + ll0 + 1]       = __float2half(c[1]);
                if ((unsigned)(ll0+8) < 128u) CkD[(rr + 8) * CKD_LD + ll0 + 8] = __float2half(c[2]);
                if ((unsigned)(ll0+9) < 128u) CkD[(rr + 8) * CKD_LD + ll0 + 9] = __float2half(c[3]);
            }
    }

    int wm = wid >> 1, wn = wid & 1;
    float acc[32];
    #pragma unroll
    for (int i = 0; i < 32; i++) acc[i] = 0.f;
    wgemm_k64<4>(Qh + wm * 32 * LDT, Kh + wn * 32 * LDT, acc, lane);
    wgemm_k64<4>(Ql + wm * 32 * LDT, Kh + wn * 32 * LDT, acc, lane);
    __syncthreads();

    #pragma unroll
    for (int m = 0; m < 2; m++)
        #pragma unroll
        for (int n = 0; n < 4; n++) {
            float* c = acc + (m * 4 + n) * 4;
            int lrow = wm * 32 + m * 16 + (lane >> 2);
            int rr   = wn * 32 + n * 8 + ((lane & 3) << 1);
            #pragma unroll
            for (int hi = 0; hi < 2; hi++) {
                int ll = lrow + hi * 8;
                float s0 = (c[hi * 2 + 0]
                            + __half2float(CqD[ll * LDT + rr])
                            + __half2float(CkD[rr * CKD_LD + ll])) * 0.125f
                           + mask_s[rr];
                float s1 = (c[hi * 2 + 1]
                            + __half2float(CqD[ll * LDT + rr + 1])
                            + __half2float(CkD[(rr + 1) * CKD_LD + ll])) * 0.125f
                           + mask_s[rr + 1];
                *(float2*)(g_S + ((size_t)bh * S_LEN + l0 + ll) * S_LEN + r0 + rr)
                    = make_float2(s0, s1);
            }
        }
}

// =============================================================================
// Kernel 3: row softmax -> fp16 probs (hi only).  256 threads = 8 rows/CTA,
// float4 loads, half2 stores.  FMA-pipe exp.
// =============================================================================
__global__ __launch_bounds__(256) void softmax_kernel()
{
    int warp = threadIdx.x >> 5, lane = threadIdx.x & 31;
    size_t rowi = (size_t)blockIdx.x * 8 + warp;
    const float4* p4 = (const float4*)(g_S + rowi * S_LEN);
    __half2* ph2 = (__half2*)(g_Ph + rowi * S_LEN);

    float4 x[8];
    #pragma unroll
    for (int i = 0; i < 8; i++) x[i] = p4[lane + (i << 5)];

    float m = fmaxf(fmaxf(x[0].x, x[0].y), fmaxf(x[0].z, x[0].w));
    #pragma unroll
    for (int i = 1; i < 8; i++)
        m = fmaxf(m, fmaxf(fmaxf(x[i].x, x[i].y), fmaxf(x[i].z, x[i].w)));
    #pragma unroll
    for (int o = 16; o; o >>= 1) m = fmaxf(m, __shfl_xor_sync(0xffffffffu, m, o));

    float sum = 0.f;
    #pragma unroll
    for (int i = 0; i < 8; i++) {
        x[i].x = fast_exp(x[i].x - m);
        x[i].y = fast_exp(x[i].y - m);
        x[i].z = fast_exp(x[i].z - m);
        x[i].w = fast_exp(x[i].w - m);
        sum += (x[i].x + x[i].y) + (x[i].z + x[i].w);
    }
    #pragma unroll
    for (int o = 16; o; o >>= 1) sum += __shfl_xor_sync(0xffffffffu, sum, o);

    float inv = 1.0f / sum;
    #pragma unroll
    for (int i = 0; i < 8; i++) {
        int idx = (lane + (i << 5)) << 1;
        ph2[idx]     = __halves2half2(__float2half(x[i].x * inv),
                                      __float2half(x[i].y * inv));
        ph2[idx + 1] = __halves2half2(__float2half(x[i].z * inv),
                                      __float2half(x[i].w * inv));
    }
}

// =============================================================================
// Kernel 4: ctx = P @ V, 2-term (Ph·Vh + Ph·Vl = Ph·V), cp.async
// double-buffered. 128(l) x 64(d) / CTA, K=1024 in 16 chunks, 8 warps.
// buffer (halfs): Pth @0 (128) | Vth @128*LDT (64) | Vtl @192*LDT (64)
// 36864 B/buffer, 73728 total -> 2+ CTAs/SM.
// =============================================================================
#define PV_BUF  18432
#define PV_SMEM (2 * 36864)
__global__ __launch_bounds__(256) void pv_mma_kernel(float* __restrict__ out)
{
    extern __shared__ __half sh[];
    int tid = threadIdx.x, wid = tid >> 5, lane = tid & 31;
    int wm = wid >> 1, wn = wid & 1;
    int bh = blockIdx.y, l0 = blockIdx.x << 7;
    int b = bh / NHEADS, h = bh % NHEADS;

    const __half* Php = g_Ph + ((size_t)bh * S_LEN + l0) * S_LEN;
    const __half* Vhp = g_VTh + (size_t)bh * (HDIM * S_LEN);
    const __half* Vlp = g_VTl + (size_t)bh * (HDIM * S_LEN);

    float acc[32];
    #pragma unroll
    for (int i = 0; i < 32; i++) acc[i] = 0.f;

    {
        __half* B = sh;
        ldtile_cp(B,             Php, 128, S_LEN, tid, 256);
        ldtile_cp(B + 128 * LDT, Vhp,  64, S_LEN, tid, 256);
        ldtile_cp(B + 192 * LDT, Vlp,  64, S_LEN, tid, 256);
        CP_COMMIT();
    }

    for (int c = 0; c < 16; c++) {
        __half* cur = sh + (c & 1) * PV_BUF;
        if (c + 1 < 16) {
            __half* nxt = sh + ((c + 1) & 1) * PV_BUF;
            int kt = (c + 1) * 64;
            ldtile_cp(nxt,             Php + kt, 128, S_LEN, tid, 256);
            ldtile_cp(nxt + 128 * LDT, Vhp + kt,  64, S_LEN, tid, 256);
            ldtile_cp(nxt + 192 * LDT, Vlp + kt,  64, S_LEN, tid, 256);
            CP_COMMIT();
            CP_WAIT1();
        } else {
            CP_WAIT0();
        }
        __syncthreads();
        wgemm_k64<4>(cur + wm * 32 * LDT, cur + 128 * LDT + wn * 32 * LDT, acc, lane);
        wgemm_k64<4>(cur + wm * 32 * LDT, cur + 192 * LDT + wn * 32 * LDT, acc, lane);
        __syncthreads();
    }

    #pragma unroll
    for (int m = 0; m < 2; m++)
        #pragma unroll
        for (int n = 0; n < 4; n++) {
            float* c = acc + (m * 4 + n) * 4;
            int lrow = wm * 32 + m * 16 + (lane >> 2);
            int d    = wn * 32 + n * 8 + ((lane & 3) << 1);
            float* o0 = out + ((size_t)b * S_LEN + l0 + lrow) * HID + h * HDIM + d;
            *(float2*)o0 = make_float2(c[0], c[1]);
            float* o1 = o0 + 8 * HID;
            *(float2*)o1 = make_float2(c[2], c[3]);
        }
}

// =============================================================================
extern "C" void kernel_launch(void* const* d_in, const int* in_sizes, int n_in,
                              void* d_out, int out_size)
{
    const float* hidden = (const float*)d_in[0];
    const float* mask   = (const float*)d_in[1];
    const float* Wq     = (const float*)d_in[2];
    const float* bq     = (const float*)d_in[3];
    const float* Wk     = (const float*)d_in[4];
    const float* bk     = (const float*)d_in[5];
    const float* Wv     = (const float*)d_in[6];
    const float* bv     = (const float*)d_in[7];
    const float* dist   = (const float*)d_in[8];
    float* out          = (float*)d_out;

    cudaFuncSetAttribute(qkv_mma_kernel,
                         cudaFuncAttributeMaxDynamicSharedMemorySize, QKV_SMEM);
    cudaFuncSetAttribute(scores_mma_kernel,
                         cudaFuncAttributeMaxDynamicSharedMemorySize, SC_SMEM);
    cudaFuncSetAttribute(pv_mma_kernel,
                         cudaFuncAttributeMaxDynamicSharedMemorySize, PV_SMEM);

    split_x_kernel<<<(MTOT * HID) / 256, 256>>>(hidden);
    conv_w_kernel<<<dim3((HID * HID) / 256, 3), 256>>>(Wq, Wk, Wv);
    prep_dist_kernel<<<(DROWS * 64) / 256, 256>>>(dist);
    qkv_mma_kernel<<<dim3(32, 12, 3), 256, QKV_SMEM>>>(bq, bk, bv);
    vt_kernel<<<dim3(16, BH), 256>>>();
    scores_mma_kernel<<<dim3(16, 8, BH), 256, SC_SMEM>>>(mask);
    softmax_kernel<<<(BH * S_LEN) / 8, 256>>>();
    pv_mma_kernel<<<dim3(8, BH), 256, PV_SMEM>>>(out);
}

// round 16
// speedup vs baseline: 1.2200x; 1.0333x over previous
#include <cuda_runtime.h>
#include <cuda_fp16.h>
#include <cstdint>
#include <cstddef>

#define NHEADS 12
#define HDIM   64
#define S_LEN  1024
#define BATCH  4
#define HID    768
#define BH     (BATCH * NHEADS)   // 48
#define DROWS  2048
#define MTOT   (BATCH * S_LEN)    // 4096

// ---------------- scratch (__device__ globals; no allocation) ----------------
__device__ __half g_Xh[MTOT * HID];                    // hidden split hi
__device__ __half g_Xl[MTOT * HID];                    // hidden split lo
__device__ __half g_Wh[3 * HID * HID];                 // Wq|Wk|Wv fp16
__device__ __half g_Qh[BH * S_LEN * HDIM];
__device__ __half g_Ql[BH * S_LEN * HDIM];
__device__ __half g_Kh[BH * S_LEN * HDIM];
__device__ float  g_V [BH * S_LEN * HDIM];
__device__ __half g_VTh[BH * HDIM * S_LEN];            // [bh][d][s] hi
__device__ __half g_VTl[BH * HDIM * S_LEN];            // [bh][d][s] lo
__device__ __half g_Dh[DROWS * HDIM];                  // padded dist fp16
__device__ float  g_S[(size_t)BH * S_LEN * S_LEN];     // scores fp32
__device__ __half g_Ph[(size_t)BH * S_LEN * S_LEN];    // probs fp16 (hi only)

// ===================== mma.sync / cp.async helpers (sm_80+) ==================
__device__ __forceinline__ uint32_t smem_u32(const void* p) {
    uint32_t a;
    asm("{ .reg .u64 t; cvta.to.shared.u64 t, %1; cvt.u32.u64 %0, t; }"
        : "=r"(a) : "l"(p));
    return a;
}
__device__ __forceinline__ void ldsm_x4(uint32_t r[4], uint32_t addr) {
    asm volatile("ldmatrix.sync.aligned.m8n8.x4.shared.b16 {%0,%1,%2,%3}, [%4];"
                 : "=r"(r[0]), "=r"(r[1]), "=r"(r[2]), "=r"(r[3]) : "r"(addr));
}
__device__ __forceinline__ void mma16816(float* c, const uint32_t a[4],
                                         uint32_t b0, uint32_t b1) {
    asm volatile("mma.sync.aligned.m16n8k16.row.col.f32.f16.f16.f32 "
                 "{%0,%1,%2,%3}, {%4,%5,%6,%7}, {%8,%9}, {%0,%1,%2,%3};"
                 : "+f"(c[0]), "+f"(c[1]), "+f"(c[2]), "+f"(c[3])
                 : "r"(a[0]), "r"(a[1]), "r"(a[2]), "r"(a[3]), "r"(b0), "r"(b1));
}
__device__ __forceinline__ void cp16(void* sdst, const void* gsrc) {
    asm volatile("cp.async.cg.shared.global [%0], [%1], 16;"
                 :: "r"(smem_u32(sdst)), "l"(gsrc));
}
#define CP_COMMIT() asm volatile("cp.async.commit_group;")
#define CP_WAIT1()  asm volatile("cp.async.wait_group 1;")
#define CP_WAIT0()  asm volatile("cp.async.wait_group 0;")

#define LDT 72   // smem tile stride in halfs (144 B: conflict-free ldmatrix)

// Warp GEMM: C[32 x NT*8] += A[32 x 64] * B[NT*8 x 64]^T ; A[m][k], B[n][k].
template<int NT>
__device__ __forceinline__ void wgemm_k64(const __half* As, const __half* Bs,
                                          float* acc, int lane)
{
    #pragma unroll
    for (int k = 0; k < 4; k++) {
        uint32_t a[2][4];
        #pragma unroll
        for (int m = 0; m < 2; m++) {
            uint32_t addr = smem_u32(As + (m * 16 + (lane & 15)) * LDT
                                        + k * 16 + ((lane >> 4) << 3));
            ldsm_x4(a[m], addr);
        }
        uint32_t b[NT][2];
        #pragma unroll
        for (int np = 0; np < NT / 2; np++) {
            uint32_t r[4];
            uint32_t addr = smem_u32(Bs + (np * 16 + (lane & 7) + ((lane >> 4) << 3)) * LDT
                                        + k * 16 + (((lane >> 3) & 1) << 3));
            ldsm_x4(r, addr);
            b[2*np][0] = r[0]; b[2*np][1] = r[1];
            b[2*np+1][0] = r[2]; b[2*np+1][1] = r[3];
        }
        #pragma unroll
        for (int m = 0; m < 2; m++)
            #pragma unroll
            for (int n = 0; n < NT; n++)
                mma16816(acc + (m * NT + n) * 4, a[m], b[n][0], b[n][1]);
    }
}

// synchronous tile copy (scores kernel)
__device__ __forceinline__ void ldtile16(__half* dst, const __half* src,
                                         int rows, int rs, int tid, int nthr) {
    for (int idx = tid; idx < rows * 8; idx += nthr) {
        int r = idx >> 3, v = idx & 7;
        uint4 x = *(const uint4*)(src + (size_t)r * rs + v * 8);
        *(uint4*)(dst + r * LDT + v * 8) = x;
    }
}
// async tile copy via cp.async (16B each)
__device__ __forceinline__ void ldtile_cp(__half* dst, const __half* src,
                                          int rows, int rs, int tid, int nthr) {
    for (int idx = tid; idx < rows * 8; idx += nthr) {
        int r = idx >> 3, v = idx & 7;
        cp16(dst + r * LDT + v * 8, src + (size_t)r * rs + v * 8);
    }
}

__device__ __forceinline__ float fast_exp(float x)
{
    float y = x * 1.4426950408889634f;
    y = fmaxf(y, -120.f);
    float r = rintf(y);
    float f = y - r;
    float z = f * 0.6931471805599453f;
    float p = fmaf(z, 0.008333333f, 0.041666668f);
    p = fmaf(z, p, 0.16666667f);
    p = fmaf(z, p, 0.5f);
    p = fmaf(z, p, 1.0f);
    p = fmaf(z, p, 1.0f);
    int e = (int)r;
    float s = __int_as_float((e + 127) << 23);
    return s * p;
}

// =============================================================================
// Prep kernels
// =============================================================================
__global__ __launch_bounds__(256) void split_x_kernel(const float* __restrict__ X)
{
    int idx = blockIdx.x * 256 + threadIdx.x;
    float v = X[idx];
    __half h = __float2half(v);
    g_Xh[idx] = h;
    g_Xl[idx] = __float2half(v - __half2float(h));
}
__global__ __launch_bounds__(256) void conv_w_kernel(
    const float* __restrict__ Wq, const float* __restrict__ Wk,
    const float* __restrict__ Wv)
{
    int z = blockIdx.y;
    const float* W = (z == 0) ? Wq : (z == 1) ? Wk : Wv;
    int idx = blockIdx.x * 256 + threadIdx.x;
    g_Wh[z * HID * HID + idx] = __float2half(W[idx]);
}
__global__ __launch_bounds__(256) void prep_dist_kernel(const float* __restrict__ dist)
{
    int idx = blockIdx.x * 256 + threadIdx.x;
    int t = idx >> 6;
    float v = (t < 2047) ? dist[idx] : 0.f;
    g_Dh[idx] = __float2half(v);
}

// =============================================================================
// Kernel 1: QKV projection, 2-term compensated (XhWh + XlWh), cp.async
// double-buffered.  128(m) x 128(n) tile / CTA, 256 threads (4x2 warps,
// 32(m) x 64(n) each), K=768 in 12 chunks of 64.  2 CTAs/SM.
// buffer (halfs): Xh @0 (128 rows) | Xl @128*LDT | Wh @256*LDT (128 rows)
// = 384 rows x 144 B = 55296 B per buffer.
// =============================================================================
#define QKV_BUF  27648   // halfs per buffer
#define QKV_SMEM (2 * 55296)
__global__ __launch_bounds__(256) void qkv_mma_kernel(
    const float* __restrict__ bq, const float* __restrict__ bk,
    const float* __restrict__ bv)
{
    extern __shared__ __half sh[];
    int tid = threadIdx.x, wid = tid >> 5, lane = tid & 31;
    int wm = wid >> 1, wn = wid & 1;          // 4x2 warps, 32(m) x 64(n)
    int m0 = blockIdx.x << 7, n0 = blockIdx.y << 7;
    int z = blockIdx.z;
    const float* bias = (z == 0) ? bq : (z == 1) ? bk : bv;

    const __half* Xhp = g_Xh + (size_t)m0 * HID;
    const __half* Xlp = g_Xl + (size_t)m0 * HID;
    const __half* Whp = g_Wh + (size_t)z * HID * HID + (size_t)n0 * HID;

    float acc[64];
    #pragma unroll
    for (int i = 0; i < 64; i++) acc[i] = 0.f;

    {
        __half* B = sh;
        ldtile_cp(B,             Xhp, 128, HID, tid, 256);
        ldtile_cp(B + 128 * LDT, Xlp, 128, HID, tid, 256);
        ldtile_cp(B + 256 * LDT, Whp, 128, HID, tid, 256);
        CP_COMMIT();
    }

    for (int c = 0; c < 12; c++) {
        __half* cur = sh + (c & 1) * QKV_BUF;
        if (c + 1 < 12) {
            __half* nxt = sh + ((c + 1) & 1) * QKV_BUF;
            int kt = (c + 1) * 64;
            ldtile_cp(nxt,             Xhp + kt, 128, HID, tid, 256);
            ldtile_cp(nxt + 128 * LDT, Xlp + kt, 128, HID, tid, 256);
            ldtile_cp(nxt + 256 * LDT, Whp + kt, 128, HID, tid, 256);
            CP_COMMIT();
            CP_WAIT1();
        } else {
            CP_WAIT0();
        }
        __syncthreads();
        wgemm_k64<8>(cur + wm * 32 * LDT,             cur + 256 * LDT + wn * 64 * LDT, acc, lane);
        wgemm_k64<8>(cur + 128 * LDT + wm * 32 * LDT, cur + 256 * LDT + wn * 64 * LDT, acc, lane);
        __syncthreads();
    }

    #pragma unroll
    for (int m = 0; m < 2; m++)
        #pragma unroll
        for (int n = 0; n < 8; n++) {
            float* c = acc + (m * 8 + n) * 4;
            int mrow = m0 + wm * 32 + m * 16 + (lane >> 2);
            int ncol = n0 + wn * 64 + n * 8 + ((lane & 3) << 1);
            #pragma unroll
            for (int hi = 0; hi < 2; hi++) {
                int mr = mrow + hi * 8;
                int bb = mr >> 10, s = mr & 1023;
                #pragma unroll
                for (int cc = 0; cc < 2; cc++) {
                    int n_g = ncol + cc;
                    int h = n_g >> 6, d = n_g & 63;
                    size_t idx = (((size_t)(bb * NHEADS + h)) * S_LEN + s) * HDIM + d;
                    float val = c[hi * 2 + cc] + bias[n_g];
                    if (z == 2) {
                        g_V[idx] = val;
                    } else if (z == 1) {
                        g_Kh[idx] = __float2half(val);
                    } else {
                        __half hv = __float2half(val);
                        g_Qh[idx] = hv;
                        g_Ql[idx] = __float2half(val - __half2float(hv));
                    }
                }
            }
        }
}

// =============================================================================
// Kernel 1c: V transpose [bh][s][d] f32 -> [bh][d][s] fp16 hi/lo
// =============================================================================
__global__ __launch_bounds__(256) void vt_kernel()
{
    __shared__ float st[64 * 65];
    int bh = blockIdx.y, s0 = blockIdx.x << 6;
    const float* Vp = g_V + (size_t)bh * (S_LEN * HDIM);
    for (int idx = threadIdx.x; idx < 4096; idx += 256) {
        int sl = idx >> 6, d = idx & 63;
        st[d * 65 + sl] = Vp[(size_t)(s0 + sl) * 64 + d];
    }
    __syncthreads();
    for (int idx = threadIdx.x; idx < 4096; idx += 256) {
        int d = idx >> 6, sl = idx & 63;
        float v = st[d * 65 + sl];
        __half hv = __float2half(v);
        size_t o = ((size_t)bh * 64 + d) * S_LEN + s0 + sl;
        g_VTh[o] = hv;
        g_VTl[o] = __float2half(v - __half2float(hv));
    }
}

// =============================================================================
// Kernel 2: scores, 128(l) x 64(r) tile / CTA, 2 CTAs/SM (109.8 KB smem).
//   j = ll - rr + 63 in [0,190]; window Dw = D[t0 .. t0+191], t0 = l0-r0+960.
//   Cq is WINDOWED: a 32-row group [R,R+32) only needs j in [R, R+95]
//   (rr<64 => j = ll-rr+63 in [ll, ll+63]), so each warp computes its own
//   96-wide shifted window -> half the Cq MMA work vs full 192.
//   Bands in diagonal form: CqD[ll][rr], CkD[rr][ll].
//   epilogue: (QK + CqD + CkD) * 0.125 + mask[rr] -> g_S fp32
// =============================================================================
#define CKD_LD 136
#define SC_SMEM 109824
__global__ __launch_bounds__(256, 2) void scores_mma_kernel(const float* __restrict__ mask)
{
    extern __shared__ __half sh[];
    __half* Qh  = sh;
    __half* Ql  = sh + 9216;
    __half* Kh  = sh + 18432;
    __half* Dw  = sh + 23040;
    __half* CqD = sh + 36864;
    __half* CkD = sh + 46080;
    float*  mask_s = (float*)((char*)sh + 109568);

    int tid = threadIdx.x, wid = tid >> 5, lane = tid & 31;
    int bh = blockIdx.z, b = bh / NHEADS;
    int l0 = blockIdx.y << 7, r0 = blockIdx.x << 6;
    int t0 = l0 - r0 + 960;

    size_t qoff = (size_t)bh * (S_LEN * HDIM) + (size_t)l0 * 64;
    size_t koff = (size_t)bh * (S_LEN * HDIM) + (size_t)r0 * 64;
    ldtile16(Qh, g_Qh + qoff, 128, 64, tid, 256);
    ldtile16(Ql, g_Ql + qoff, 128, 64, tid, 256);
    ldtile16(Kh, g_Kh + koff,  64, 64, tid, 256);
    ldtile16(Dw, g_Dh + (size_t)t0 * 64, 192, 64, tid, 256);
    if (tid < 64) mask_s[tid] = mask[b * S_LEN + r0 + tid];
    __syncthreads();

    // ---- Cq (windowed): warp (wm,wj): rows [R,R+32), j in [R+wj*48, R+wj*48+48)
    {
        int wm = wid >> 1, wj = wid & 1;
        int R = wm * 32;
        int jb = R + wj * 48;
        float acc[48];
        #pragma unroll
        for (int i = 0; i < 48; i++) acc[i] = 0.f;
        wgemm_k64<6>(Qh + R * LDT, Dw + jb * LDT, acc, lane);
        #pragma unroll
        for (int m = 0; m < 2; m++)
            #pragma unroll
            for (int n = 0; n < 6; n++) {
                float* c = acc + (m * 6 + n) * 4;
                int row = R + m * 16 + (lane >> 2);
                int j   = jb + n * 8 + ((lane & 3) << 1);
                int rr0 = row + 63 - j;
                if ((unsigned)rr0 < 64u)     CqD[row * LDT + rr0]           = __float2half(c[0]);
                if ((unsigned)(rr0-1) < 64u) CqD[row * LDT + rr0 - 1]       = __float2half(c[1]);
                if ((unsigned)(rr0+8) < 64u) CqD[(row + 8) * LDT + rr0 + 8] = __float2half(c[2]);
                if ((unsigned)(rr0+7) < 64u) CqD[(row + 8) * LDT + rr0 + 7] = __float2half(c[3]);
            }
    }
    // ---- Ck: warp = (wr: r-block of 32) x (wj4: j-block of 48), full window
    {
        int wr = wid >> 2, wj4 = wid & 3;
        float acc[48];
        #pragma unroll
        for (int i = 0; i < 48; i++) acc[i] = 0.f;
        int jb = wj4 * 48;
        wgemm_k64<6>(Kh + wr * 32 * LDT, Dw + jb * LDT, acc, lane);
        #pragma unroll
        for (int m = 0; m < 2; m++)
            #pragma unroll
            for (int n = 0; n < 6; n++) {
                float* c = acc + (m * 6 + n) * 4;
                int rr = wr * 32 + m * 16 + (lane >> 2);
                int j  = jb + n * 8 + ((lane & 3) << 1);
                int ll0 = j + rr - 63;
                if ((unsigned)ll0 < 128u)     CkD[rr * CKD_LD + ll0]           = __float2half(c[0]);
                if ((unsigned)(ll0+1) < 128u) CkD[rr * CKD_LD + ll0 + 1]       = __float2half(c[1]);
                if ((unsigned)(ll0+8) < 128u) CkD[(rr + 8) * CKD_LD + ll0 + 8] = __float2half(c[2]);
                if ((unsigned)(ll0+9) < 128u) CkD[(rr + 8) * CKD_LD + ll0 + 9] = __float2half(c[3]);
            }
    }

    // ---- QK: warp = (wm: l-block 32) x (wn: r-block 32)
    int wm = wid >> 1, wn = wid & 1;
    float acc[32];
    #pragma unroll
    for (int i = 0; i < 32; i++) acc[i] = 0.f;
    wgemm_k64<4>(Qh + wm * 32 * LDT, Kh + wn * 32 * LDT, acc, lane);
    wgemm_k64<4>(Ql + wm * 32 * LDT, Kh + wn * 32 * LDT, acc, lane);
    __syncthreads();   // bands complete

    #pragma unroll
    for (int m = 0; m < 2; m++)
        #pragma unroll
        for (int n = 0; n < 4; n++) {
            float* c = acc + (m * 4 + n) * 4;
            int lrow = wm * 32 + m * 16 + (lane >> 2);
            int rr   = wn * 32 + n * 8 + ((lane & 3) << 1);
            #pragma unroll
            for (int hi = 0; hi < 2; hi++) {
                int ll = lrow + hi * 8;
                float s0 = (c[hi * 2 + 0]
                            + __half2float(CqD[ll * LDT + rr])
                            + __half2float(CkD[rr * CKD_LD + ll])) * 0.125f
                           + mask_s[rr];
                float s1 = (c[hi * 2 + 1]
                            + __half2float(CqD[ll * LDT + rr + 1])
                            + __half2float(CkD[(rr + 1) * CKD_LD + ll])) * 0.125f
                           + mask_s[rr + 1];
                *(float2*)(g_S + ((size_t)bh * S_LEN + l0 + ll) * S_LEN + r0 + rr)
                    = make_float2(s0, s1);
            }
        }
}

// =============================================================================
// Kernel 3: row softmax -> fp16 probs (hi only).  256 threads = 8 rows/CTA,
// float4 loads, half2 stores.  FMA-pipe exp.
// =============================================================================
__global__ __launch_bounds__(256) void softmax_kernel()
{
    int warp = threadIdx.x >> 5, lane = threadIdx.x & 31;
    size_t rowi = (size_t)blockIdx.x * 8 + warp;
    const float4* p4 = (const float4*)(g_S + rowi * S_LEN);
    __half2* ph2 = (__half2*)(g_Ph + rowi * S_LEN);

    float4 x[8];
    #pragma unroll
    for (int i = 0; i < 8; i++) x[i] = p4[lane + (i << 5)];

    float m = fmaxf(fmaxf(x[0].x, x[0].y), fmaxf(x[0].z, x[0].w));
    #pragma unroll
    for (int i = 1; i < 8; i++)
        m = fmaxf(m, fmaxf(fmaxf(x[i].x, x[i].y), fmaxf(x[i].z, x[i].w)));
    #pragma unroll
    for (int o = 16; o; o >>= 1) m = fmaxf(m, __shfl_xor_sync(0xffffffffu, m, o));

    float sum = 0.f;
    #pragma unroll
    for (int i = 0; i < 8; i++) {
        x[i].x = fast_exp(x[i].x - m);
        x[i].y = fast_exp(x[i].y - m);
        x[i].z = fast_exp(x[i].z - m);
        x[i].w = fast_exp(x[i].w - m);
        sum += (x[i].x + x[i].y) + (x[i].z + x[i].w);
    }
    #pragma unroll
    for (int o = 16; o; o >>= 1) sum += __shfl_xor_sync(0xffffffffu, sum, o);

    float inv = 1.0f / sum;
    #pragma unroll
    for (int i = 0; i < 8; i++) {
        int idx = (lane + (i << 5)) << 1;
        ph2[idx]     = __halves2half2(__float2half(x[i].x * inv),
                                      __float2half(x[i].y * inv));
        ph2[idx + 1] = __halves2half2(__float2half(x[i].z * inv),
                                      __float2half(x[i].w * inv));
    }
}

// =============================================================================
// Kernel 4: ctx = P @ V, 2-term (Ph·Vh + Ph·Vl = Ph·V), cp.async
// double-buffered. 128(l) x 64(d) / CTA, K=1024 in 16 chunks, 8 warps.
// buffer (halfs): Pth @0 (128) | Vth @128*LDT (64) | Vtl @192*LDT (64)
// =============================================================================
#define PV_BUF  18432
#define PV_SMEM (2 * 36864)
__global__ __launch_bounds__(256) void pv_mma_kernel(float* __restrict__ out)
{
    extern __shared__ __half sh[];
    int tid = threadIdx.x, wid = tid >> 5, lane = tid & 31;
    int wm = wid >> 1, wn = wid & 1;
    int bh = blockIdx.y, l0 = blockIdx.x << 7;
    int b = bh / NHEADS, h = bh % NHEADS;

    const __half* Php = g_Ph + ((size_t)bh * S_LEN + l0) * S_LEN;
    const __half* Vhp = g_VTh + (size_t)bh * (HDIM * S_LEN);
    const __half* Vlp = g_VTl + (size_t)bh * (HDIM * S_LEN);

    float acc[32];
    #pragma unroll
    for (int i = 0; i < 32; i++) acc[i] = 0.f;

    {
        __half* B = sh;
        ldtile_cp(B,             Php, 128, S_LEN, tid, 256);
        ldtile_cp(B + 128 * LDT, Vhp,  64, S_LEN, tid, 256);
        ldtile_cp(B + 192 * LDT, Vlp,  64, S_LEN, tid, 256);
        CP_COMMIT();
    }

    for (int c = 0; c < 16; c++) {
        __half* cur = sh + (c & 1) * PV_BUF;
        if (c + 1 < 16) {
            __half* nxt = sh + ((c + 1) & 1) * PV_BUF;
            int kt = (c + 1) * 64;
            ldtile_cp(nxt,             Php + kt, 128, S_LEN, tid, 256);
            ldtile_cp(nxt + 128 * LDT, Vhp + kt,  64, S_LEN, tid, 256);
            ldtile_cp(nxt + 192 * LDT, Vlp + kt,  64, S_LEN, tid, 256);
            CP_COMMIT();
            CP_WAIT1();
        } else {
            CP_WAIT0();
        }
        __syncthreads();
        wgemm_k64<4>(cur + wm * 32 * LDT, cur + 128 * LDT + wn * 32 * LDT, acc, lane);
        wgemm_k64<4>(cur + wm * 32 * LDT, cur + 192 * LDT + wn * 32 * LDT, acc, lane);
        __syncthreads();
    }

    #pragma unroll
    for (int m = 0; m < 2; m++)
        #pragma unroll
        for (int n = 0; n < 4; n++) {
            float* c = acc + (m * 4 + n) * 4;
            int lrow = wm * 32 + m * 16 + (lane >> 2);
            int d    = wn * 32 + n * 8 + ((lane & 3) << 1);
            float* o0 = out + ((size_t)b * S_LEN + l0 + lrow) * HID + h * HDIM + d;
            *(float2*)o0 = make_float2(c[0], c[1]);
            float* o1 = o0 + 8 * HID;
            *(float2*)o1 = make_float2(c[2], c[3]);
        }
}

// =============================================================================
extern "C" void kernel_launch(void* const* d_in, const int* in_sizes, int n_in,
                              void* d_out, int out_size)
{
    const float* hidden = (const float*)d_in[0];
    const float* mask   = (const float*)d_in[1];
    const float* Wq     = (const float*)d_in[2];
    const float* bq     = (const float*)d_in[3];
    const float* Wk     = (const float*)d_in[4];
    const float* bk     = (const float*)d_in[5];
    const float* Wv     = (const float*)d_in[6];
    const float* bv     = (const float*)d_in[7];
    const float* dist   = (const float*)d_in[8];
    float* out          = (float*)d_out;

    cudaFuncSetAttribute(qkv_mma_kernel,
                         cudaFuncAttributeMaxDynamicSharedMemorySize, QKV_SMEM);
    cudaFuncSetAttribute(scores_mma_kernel,
                         cudaFuncAttributeMaxDynamicSharedMemorySize, SC_SMEM);
    cudaFuncSetAttribute(pv_mma_kernel,
                         cudaFuncAttributeMaxDynamicSharedMemorySize, PV_SMEM);

    split_x_kernel<<<(MTOT * HID) / 256, 256>>>(hidden);
    conv_w_kernel<<<dim3((HID * HID) / 256, 3), 256>>>(Wq, Wk, Wv);
    prep_dist_kernel<<<(DROWS * 64) / 256, 256>>>(dist);
    qkv_mma_kernel<<<dim3(32, 6, 3), 256, QKV_SMEM>>>(bq, bk, bv);
    vt_kernel<<<dim3(16, BH), 256>>>();
    scores_mma_kernel<<<dim3(16, 8, BH), 256, SC_SMEM>>>(mask);
    softmax_kernel<<<(BH * S_LEN) / 8, 256>>>();
    pv_mma_kernel<<<dim3(8, BH), 256, PV_SMEM>>>(out);
}